// round 1
// baseline (speedup 1.0000x reference)
#include <cuda_runtime.h>

// ---------------------------------------------------------------------------
// LieSpline: SE(3) cubic B-spline interpolation.
// B=32, N=2048 poses (t[3], q[4] xyzw), K=32 time samples.
// Output: (B, (N-1)*K, 7) float32.
//
// Kernel 1: delta[b][j] = se3_log( inv(P[j]) * P[j+1] ) over padded pose array
//           (j = 0..N, endpoints are exactly zero).
// Kernel 2: one warp per (b, segment), one lane per time sample k.
// ---------------------------------------------------------------------------

#define LS_B 32
#define LS_N 2048
#define LS_J (LS_N + 1)   // 2049 deltas per batch

__device__ float g_delta[LS_B * LS_J * 6];

__device__ __forceinline__ float3 f3(float x, float y, float z) {
    return make_float3(x, y, z);
}
__device__ __forceinline__ float3 cross3(const float3 a, const float3 b) {
    return make_float3(a.y * b.z - a.z * b.y,
                       a.z * b.x - a.x * b.z,
                       a.x * b.y - a.y * b.x);
}
__device__ __forceinline__ float dot3(const float3 a, const float3 b) {
    return a.x * b.x + a.y * b.y + a.z * b.z;
}
// rotate v by quaternion q (xyzw)
__device__ __forceinline__ float3 qrot(const float4 q, const float3 v) {
    float3 qv = f3(q.x, q.y, q.z);
    float3 t = cross3(qv, v);
    t.x *= 2.0f; t.y *= 2.0f; t.z *= 2.0f;
    float3 c = cross3(qv, t);
    return f3(v.x + q.w * t.x + c.x,
              v.y + q.w * t.y + c.y,
              v.z + q.w * t.z + c.z);
}
__device__ __forceinline__ float4 qmul(const float4 a, const float4 b) {
    return make_float4(
        a.w * b.x + a.x * b.w + a.y * b.z - a.z * b.y,
        a.w * b.y + a.y * b.w + a.z * b.x - a.x * b.z,
        a.w * b.z + a.z * b.w + a.x * b.y - a.y * b.x,
        a.w * b.w - a.x * b.x - a.y * b.y - a.z * b.z);
}

// ---------------------------------------------------------------------------
// Kernel 1: per-(b, j) relative-pose log.
// ---------------------------------------------------------------------------
__global__ void __launch_bounds__(256) k_delta(const float* __restrict__ poses) {
    int idx = blockIdx.x * blockDim.x + threadIdx.x;
    if (idx >= LS_B * LS_J) return;
    int b = idx / LS_J;
    int j = idx - b * LS_J;
    float* o = g_delta + (size_t)idx * 6;
    if (j == 0 || j == LS_N) {
        // padded endpoints: relative pose is identity -> log is exactly 0
        o[0] = 0.f; o[1] = 0.f; o[2] = 0.f; o[3] = 0.f; o[4] = 0.f; o[5] = 0.f;
        return;
    }
    const float* pa = poses + ((size_t)b * LS_N + (j - 1)) * 7;
    float3 t0 = f3(pa[0], pa[1], pa[2]);
    float4 q0 = make_float4(pa[3], pa[4], pa[5], pa[6]);
    float3 t1 = f3(pa[7], pa[8], pa[9]);
    float4 q1 = make_float4(pa[10], pa[11], pa[12], pa[13]);

    // rel = inv(T0) * T1
    float4 qi = make_float4(-q0.x, -q0.y, -q0.z, q0.w);
    float3 dt = f3(t1.x - t0.x, t1.y - t0.y, t1.z - t0.z);
    float3 t  = qrot(qi, dt);
    float4 q  = qmul(qi, q1);

    // so3_log(q)
    float n2 = q.x * q.x + q.y * q.y + q.z * q.z;
    bool small = n2 < 1e-12f;
    float ns = small ? 1.0f : n2;
    float rn = rsqrtf(ns);     // 1/n
    float n  = ns * rn;        // n
    float factor;
    if (small) {
        float iw = __fdividef(1.0f, q.w);
        factor = 2.0f * iw - (2.0f / 3.0f) * n2 * iw * iw * iw;
    } else {
        factor = 2.0f * atan2f(n, q.w) * rn;
    }
    float3 phi = f3(factor * q.x, factor * q.y, factor * q.z);

    // jl_inv(phi, t)
    float t2 = dot3(phi, phi);
    bool sm2 = t2 < 1e-12f;
    float t2s = sm2 ? 1.0f : t2;
    float rth = rsqrtf(t2s);     // 1/theta
    float theta = t2s * rth;     // theta
    float s, cth;
    __sincosf(theta, &s, &cth);
    float s_safe = (fabsf(s) < 1e-6f) ? 1e-6f : s;
    float c;
    if (sm2) {
        c = (1.0f / 12.0f) + t2 * (1.0f / 720.0f);
    } else {
        c = rth * rth - __fdividef(1.0f + cth, 2.0f * theta * s_safe);
    }
    float3 c1 = cross3(phi, t);
    float3 c2 = cross3(phi, c1);
    o[0] = t.x - 0.5f * c1.x + c * c2.x;
    o[1] = t.y - 0.5f * c1.y + c * c2.y;
    o[2] = t.z - 0.5f * c1.z + c * c2.z;
    o[3] = phi.x;
    o[4] = phi.y;
    o[5] = phi.z;
}

// ---------------------------------------------------------------------------
// step: T <- T * se3_exp(w * delta)
// ---------------------------------------------------------------------------
__device__ __forceinline__ void step(float3& Tt, float4& Tq,
                                     const float* __restrict__ d, float wk) {
    float3 tau = f3(d[0] * wk, d[1] * wk, d[2] * wk);
    float3 phi = f3(d[3] * wk, d[4] * wk, d[5] * wk);
    float t2 = dot3(phi, phi);
    bool small = t2 < 1e-12f;
    float t2s = small ? 1.0f : t2;
    float rth = rsqrtf(t2s);     // 1/theta
    float theta = t2s * rth;
    float sh, ch;
    __sincosf(0.5f * theta, &sh, &ch);
    // so3_exp
    float qs = small ? (0.5f - t2 * (1.0f / 48.0f)) : sh * rth;
    float qw = small ? (1.0f - t2 * 0.125f) : ch;
    float4 Aq = make_float4(qs * phi.x, qs * phi.y, qs * phi.z, qw);
    // left Jacobian: a = (1-cos)/t2 = 2*sh^2/t2 (cancellation-free),
    //                b = (theta - sin)/(t2*theta), sin = 2*sh*ch
    float rt2 = rth * rth;       // 1/t2s
    float a  = small ? (0.5f - t2 * (1.0f / 24.0f)) : 2.0f * sh * sh * rt2;
    float bb = small ? ((1.0f / 6.0f) - t2 * (1.0f / 120.0f))
                     : (theta - 2.0f * sh * ch) * rt2 * rth;
    float3 c1 = cross3(phi, tau);
    float3 c2 = cross3(phi, c1);
    float3 At = f3(tau.x + a * c1.x + bb * c2.x,
                   tau.y + a * c1.y + bb * c2.y,
                   tau.z + a * c1.z + bb * c2.z);
    // T = T * A
    float3 r = qrot(Tq, At);
    Tt.x += r.x; Tt.y += r.y; Tt.z += r.z;
    Tq = qmul(Tq, Aq);
}

// ---------------------------------------------------------------------------
// Kernel 2: warp = (b, segment s), lane = time sample k (K == 32).
// ---------------------------------------------------------------------------
__global__ void __launch_bounds__(256) k_spline(const float* __restrict__ poses,
                                                const float* __restrict__ timev,
                                                float* __restrict__ out) {
    const int S = LS_N - 1;  // 2047
    int w    = threadIdx.x >> 5;
    int lane = threadIdx.x & 31;
    int pair = blockIdx.x * (blockDim.x >> 5) + w;
    if (pair >= LS_B * S) return;
    int b = pair / S;
    int s = pair - b * S;

    // spline weights for this lane's time sample
    float u  = __ldg(timev + lane);
    float u2 = u * u;
    float u3 = u2 * u;
    const float w0 = (5.0f + 3.0f * u - 3.0f * u2 + u3) * (1.0f / 6.0f);
    const float w1 = (1.0f + 3.0f * u + 3.0f * u2 - 2.0f * u3) * (1.0f / 6.0f);
    const float w2 = u3 * (1.0f / 6.0f);

    // base pose p0 = padded[s] = input[max(s-1, 0)]
    int sp = (s > 0) ? (s - 1) : 0;
    const float* pp = poses + ((size_t)b * LS_N + sp) * 7;
    float3 Tt = f3(pp[0], pp[1], pp[2]);
    float4 Tq = make_float4(pp[3], pp[4], pp[5], pp[6]);

    const float* d = g_delta + ((size_t)b * LS_J + s) * 6;
    step(Tt, Tq, d,      w0);
    step(Tt, Tq, d + 6,  w1);
    step(Tt, Tq, d + 12, w2);

    // stage through shared for coalesced 128B stores
    __shared__ float sm[8 * 224];
    float* smw = sm + w * 224;
    int o7 = lane * 7;
    smw[o7 + 0] = Tt.x; smw[o7 + 1] = Tt.y; smw[o7 + 2] = Tt.z;
    smw[o7 + 3] = Tq.x; smw[o7 + 4] = Tq.y; smw[o7 + 5] = Tq.z; smw[o7 + 6] = Tq.w;
    __syncwarp();
    float* ob = out + (size_t)pair * 224;
#pragma unroll
    for (int c = 0; c < 7; c++)
        ob[c * 32 + lane] = smw[c * 32 + lane];
}

extern "C" void kernel_launch(void* const* d_in, const int* in_sizes, int n_in,
                              void* d_out, int out_size) {
    (void)n_in; (void)out_size;
    const float* poses = (const float*)d_in[0];
    const float* timev = (const float*)d_in[1];
    float* out = (float*)d_out;

    int tot1 = LS_B * LS_J;
    k_delta<<<(tot1 + 255) / 256, 256>>>(poses);

    int pairs = LS_B * (LS_N - 1);
    k_spline<<<(pairs + 7) / 8, 256>>>(poses, timev, out);
}

// round 2
// speedup vs baseline: 1.2016x; 1.2016x over previous
#include <cuda_runtime.h>

// ---------------------------------------------------------------------------
// LieSpline: SE(3) cubic B-spline interpolation.  B=32, N=2048, K=32.
//
// Kernel 1: per padded-pair j, compute delta = se3_log(inv(P[j])P[j+1]) and
//           precompute all lane-invariant quantities for exp(w*delta):
//             tau, nd=|phi|, U=phi/nd, K2=2/nd^2, rn3=1/nd^3,
//             C1=cross(phi,tau), C2=cross(phi,C1)
//           packed as 4 float4 (64B) per delta.
// Kernel 2: warp = (b, segment), lane = time sample.  Each step is then:
//             theta=w*nd; sincos(theta/2); alpha=sh^2*K2; beta=(theta-2shch)*rn3
//             At = w*tau + alpha*C1 + beta*C2 ; Aq = (sh*U, ch)
//           -> 2 MUFU, ~60 instr per step, zero selects, zero rcp/rsqrt.
// ---------------------------------------------------------------------------

#define LS_B 32
#define LS_N 2048
#define LS_J (LS_N + 1)   // 2049 deltas per batch

__device__ float4 g_pre[LS_B * LS_J * 4];   // 4.2 MB scratch

__device__ __forceinline__ float3 f3(float x, float y, float z) {
    return make_float3(x, y, z);
}
__device__ __forceinline__ float3 cross3(const float3 a, const float3 b) {
    return make_float3(a.y * b.z - a.z * b.y,
                       a.z * b.x - a.x * b.z,
                       a.x * b.y - a.y * b.x);
}
__device__ __forceinline__ float dot3(const float3 a, const float3 b) {
    return a.x * b.x + a.y * b.y + a.z * b.z;
}
__device__ __forceinline__ float3 qrot(const float4 q, const float3 v) {
    float3 qv = f3(q.x, q.y, q.z);
    float3 t = cross3(qv, v);
    t.x *= 2.0f; t.y *= 2.0f; t.z *= 2.0f;
    float3 c = cross3(qv, t);
    return f3(v.x + q.w * t.x + c.x,
              v.y + q.w * t.y + c.y,
              v.z + q.w * t.z + c.z);
}
__device__ __forceinline__ float4 qmul(const float4 a, const float4 b) {
    return make_float4(
        a.w * b.x + a.x * b.w + a.y * b.z - a.z * b.y,
        a.w * b.y + a.y * b.w + a.z * b.x - a.x * b.z,
        a.w * b.z + a.z * b.w + a.x * b.y - a.y * b.x,
        a.w * b.w - a.x * b.x - a.y * b.y - a.z * b.z);
}

// ---------------------------------------------------------------------------
// Kernel 1: per-(b, j) relative-pose log + lane-invariant precompute.
// ---------------------------------------------------------------------------
__global__ void __launch_bounds__(256) k_delta(const float* __restrict__ poses) {
    int idx = blockIdx.x * blockDim.x + threadIdx.x;
    if (idx >= LS_B * LS_J) return;
    int b = idx / LS_J;
    int j = idx - b * LS_J;
    float4* o = g_pre + (size_t)idx * 4;
    if (j == 0 || j == LS_N) {
        // padded endpoints: relative pose is identity -> all zero
        float4 z = make_float4(0.f, 0.f, 0.f, 0.f);
        o[0] = z; o[1] = z; o[2] = z; o[3] = z;
        return;
    }
    const float* pa = poses + ((size_t)b * LS_N + (j - 1)) * 7;
    float3 t0 = f3(pa[0], pa[1], pa[2]);
    float4 q0 = make_float4(pa[3], pa[4], pa[5], pa[6]);
    float3 t1 = f3(pa[7], pa[8], pa[9]);
    float4 q1 = make_float4(pa[10], pa[11], pa[12], pa[13]);

    // rel = inv(T0) * T1
    float4 qi = make_float4(-q0.x, -q0.y, -q0.z, q0.w);
    float3 dt = f3(t1.x - t0.x, t1.y - t0.y, t1.z - t0.z);
    float3 t  = qrot(qi, dt);
    float4 q  = qmul(qi, q1);

    // so3_log(q) -> phi
    float n2 = q.x * q.x + q.y * q.y + q.z * q.z;
    bool small = n2 < 1e-12f;
    float ns = small ? 1.0f : n2;
    float rn = rsqrtf(ns);
    float n  = ns * rn;
    float factor;
    if (small) {
        float iw = __fdividef(1.0f, q.w);
        factor = 2.0f * iw - (2.0f / 3.0f) * n2 * iw * iw * iw;
    } else {
        factor = 2.0f * atan2f(n, q.w) * rn;
    }
    float3 phi = f3(factor * q.x, factor * q.y, factor * q.z);

    // jl_inv(phi, t) -> tau
    float t2 = dot3(phi, phi);
    bool sm2 = t2 < 1e-12f;
    float t2s = sm2 ? 1.0f : t2;
    float rth = rsqrtf(t2s);
    float theta = t2s * rth;
    float s, cth;
    __sincosf(theta, &s, &cth);
    float s_safe = (fabsf(s) < 1e-6f) ? 1e-6f : s;
    float c;
    if (sm2) {
        c = (1.0f / 12.0f) + t2 * (1.0f / 720.0f);
    } else {
        c = rth * rth - __fdividef(1.0f + cth, 2.0f * theta * s_safe);
    }
    float3 x1 = cross3(phi, t);
    float3 x2 = cross3(phi, x1);
    float3 tau = f3(t.x - 0.5f * x1.x + c * x2.x,
                    t.y - 0.5f * x1.y + c * x2.y,
                    t.z - 0.5f * x1.z + c * x2.z);

    // lane-invariant precompute for exp(w * (tau, phi))
    float nd2 = dot3(phi, phi);
    if (nd2 < 1e-24f) {
        // pure-translation (or zero) delta: rotation terms vanish
        o[0] = make_float4(tau.x, tau.y, tau.z, 0.f);
        float4 z = make_float4(0.f, 0.f, 0.f, 0.f);
        o[1] = z; o[2] = z; o[3] = z;
        return;
    }
    float rnd = rsqrtf(nd2);         // 1/nd
    float nd  = nd2 * rnd;           // |phi|
    float K2  = 2.0f * rnd * rnd;    // 2/nd^2
    float rn3 = rnd * rnd * rnd;     // 1/nd^3
    float3 U  = f3(phi.x * rnd, phi.y * rnd, phi.z * rnd);
    float3 C1 = cross3(phi, tau);
    float3 C2 = cross3(phi, C1);
    o[0] = make_float4(tau.x, tau.y, tau.z, nd);
    o[1] = make_float4(U.x, U.y, U.z, K2);
    o[2] = make_float4(C1.x, C1.y, C1.z, rn3);
    o[3] = make_float4(C2.x, C2.y, C2.z, 0.f);
}

// ---------------------------------------------------------------------------
// step: T <- T * exp(wk * delta)   using precomputed float4[4]
// ---------------------------------------------------------------------------
__device__ __forceinline__ void step(float3& Tt, float4& Tq,
                                     const float4* __restrict__ p, float wk) {
    float4 a0 = p[0];   // tau, nd
    float4 a1 = p[1];   // U,   2/nd^2
    float4 a2 = p[2];   // C1,  1/nd^3
    float4 a3 = p[3];   // C2,  -
    float theta = wk * a0.w;
    float sh, ch;
    __sincosf(0.5f * theta, &sh, &ch);
    float alpha = (sh * sh) * a1.w;                    // (1-cos)/nd^2 * 1? -> (1-cos th)/nd^2
    float s2 = sh + sh;
    float beta = fmaf(-s2, ch, theta) * a2.w;          // (th - sin th)/nd^3
    float3 At = f3(fmaf(beta, a3.x, fmaf(alpha, a2.x, wk * a0.x)),
                   fmaf(beta, a3.y, fmaf(alpha, a2.y, wk * a0.y)),
                   fmaf(beta, a3.z, fmaf(alpha, a2.z, wk * a0.z)));
    float4 Aq = make_float4(sh * a1.x, sh * a1.y, sh * a1.z, ch);
    float3 r = qrot(Tq, At);
    Tt.x += r.x; Tt.y += r.y; Tt.z += r.z;
    Tq = qmul(Tq, Aq);
}

// ---------------------------------------------------------------------------
// Kernel 2: warp = (b, segment s), lane = time sample k (K == 32).
// ---------------------------------------------------------------------------
__global__ void __launch_bounds__(256) k_spline(const float* __restrict__ poses,
                                                const float* __restrict__ timev,
                                                float* __restrict__ out) {
    const int S = LS_N - 1;  // 2047
    int w    = threadIdx.x >> 5;
    int lane = threadIdx.x & 31;
    int pair = blockIdx.x * (blockDim.x >> 5) + w;
    if (pair >= LS_B * S) return;
    int b = pair / S;
    int s = pair - b * S;

    // spline weights for this lane's time sample
    float u  = __ldg(timev + lane);
    float u2 = u * u;
    float u3 = u2 * u;
    const float w0 = (5.0f + 3.0f * u - 3.0f * u2 + u3) * (1.0f / 6.0f);
    const float w1 = (1.0f + 3.0f * u + 3.0f * u2 - 2.0f * u3) * (1.0f / 6.0f);
    const float w2 = u3 * (1.0f / 6.0f);

    // base pose p0 = padded[s] = input[max(s-1, 0)]
    int sp = (s > 0) ? (s - 1) : 0;
    const float* pp = poses + ((size_t)b * LS_N + sp) * 7;
    float3 Tt = f3(__ldg(pp + 0), __ldg(pp + 1), __ldg(pp + 2));
    float4 Tq = make_float4(__ldg(pp + 3), __ldg(pp + 4), __ldg(pp + 5), __ldg(pp + 6));

    const float4* pre = g_pre + ((size_t)b * LS_J + s) * 4;
    step(Tt, Tq, pre,     w0);
    step(Tt, Tq, pre + 4, w1);
    step(Tt, Tq, pre + 8, w2);

    // stage through shared for coalesced 128B stores
    __shared__ float sm[8 * 224];
    float* smw = sm + w * 224;
    int o7 = lane * 7;
    smw[o7 + 0] = Tt.x; smw[o7 + 1] = Tt.y; smw[o7 + 2] = Tt.z;
    smw[o7 + 3] = Tq.x; smw[o7 + 4] = Tq.y; smw[o7 + 5] = Tq.z; smw[o7 + 6] = Tq.w;
    __syncwarp();
    float* ob = out + (size_t)pair * 224;
#pragma unroll
    for (int c = 0; c < 7; c++)
        ob[c * 32 + lane] = smw[c * 32 + lane];
}

extern "C" void kernel_launch(void* const* d_in, const int* in_sizes, int n_in,
                              void* d_out, int out_size) {
    (void)n_in; (void)out_size;
    const float* poses = (const float*)d_in[0];
    const float* timev = (const float*)d_in[1];
    float* out = (float*)d_out;

    int tot1 = LS_B * LS_J;
    k_delta<<<(tot1 + 255) / 256, 256>>>(poses);

    int pairs = LS_B * (LS_N - 1);
    k_spline<<<(pairs + 7) / 8, 256>>>(poses, timev, out);
}